// round 4
// baseline (speedup 1.0000x reference)
#include <cuda_runtime.h>
#include <math.h>

#define D_     196
#define NCH_   64
#define H_     8
#define DH_    64
#define INNER_ 512
#define MLP_   784
#define SEQ_   65

#define NG_QKV 384   // 1536/4
#define NG_D   49    // 196/4
#define NG_MLP 196   // 784/4

// ---- scratch (__device__ globals; no allocations allowed) ----
__device__ float  g_a[NCH_ * D_];
__device__ float4 g_xatt4[SEQ_ * NG_D];
__device__ float  g_h1[SEQ_ * D_];          // LN1(x)
__device__ float4 g_qkv4[SEQ_ * NG_QKV];    // q(pre-scaled)|k|v
__device__ float4 g_o4[SEQ_ * 128];         // attention output
__device__ float4 g_x2_4[SEQ_ * NG_D];      // after attn residuals
__device__ float4 g_h2_4[SEQ_ * NG_D];      // LN2(x2)
__device__ float4 g_t4[SEQ_ * NG_MLP];      // gelu(ff1)

__device__ __forceinline__ void fma4(float4& a, float h, const float4& w) {
    a.x += h * w.x; a.y += h * w.y; a.z += h * w.z; a.w += h * w.w;
}

// ============================================================
// K1: bx<65 -> LN1 of row bx into g_h1; bx==65 -> channel gating.
// ============================================================
__global__ __launch_bounds__(256) void k_pre(
    const float* __restrict__ x, const float* __restrict__ tokens,
    const float* __restrict__ x_pe, const float* __restrict__ conv_k,
    const float* __restrict__ bn_g, const float* __restrict__ bn_b,
    const float* __restrict__ bn_rm, const float* __restrict__ bn_rv,
    const float* __restrict__ fc_w1, const float* __restrict__ fc_w2,
    const float* __restrict__ ln1_g, const float* __restrict__ ln1_b)
{
    const int tid = threadIdx.x;
    const int bx  = blockIdx.x;

    if (bx < SEQ_) {
        // ---- LN1 of row bx ----
        __shared__ float w1[8], w2[8];
        __shared__ float mean_s, rstd_s;
        const float* xr = x + bx * D_;
        float v = (tid < D_) ? xr[tid] : 0.f;
        float s1 = v, s2 = v * v;
        #pragma unroll
        for (int o = 16; o; o >>= 1) {
            s1 += __shfl_down_sync(0xffffffffu, s1, o);
            s2 += __shfl_down_sync(0xffffffffu, s2, o);
        }
        if ((tid & 31) == 0) { w1[tid >> 5] = s1; w2[tid >> 5] = s2; }
        __syncthreads();
        if (tid == 0) {
            float t1 = 0.f, t2 = 0.f;
            #pragma unroll
            for (int i = 0; i < 8; i++) { t1 += w1[i]; t2 += w2[i]; }
            float mean = t1 * (1.f / 196.f);
            float var  = t2 * (1.f / 196.f) - mean * mean;
            mean_s = mean; rstd_s = rsqrtf(var + 1e-5f);
        }
        __syncthreads();
        if (tid < D_)
            g_h1[bx * D_ + tid] = (v - mean_s) * rstd_s * ln1_g[tid] + ln1_b[tid];
        return;
    }

    // ---- gating (one block) ----
    __shared__ float b1s[NCH_];
    __shared__ float b2s[NCH_];
    __shared__ float hid[12];
    __shared__ float cs[NCH_];

    const int warp = tid >> 5, lane = tid & 31;
    const float k0 = conv_k[3], k1 = conv_k[4], k2 = conv_k[5];
    const float rm  = bn_rm[0];
    const float inv = rsqrtf(bn_rv[0] + 1e-5f) * bn_g[0];
    const float bb  = bn_b[0];

    for (int ch = warp; ch < NCH_; ch += 8) {
        const float* row = x_pe + ch * D_;
        float s = 0.f;
        for (int d = lane; d < D_; d += 32) {
            float xm = (d > 0)      ? row[d - 1] : 0.f;
            float xc = row[d];
            float xp = (d < D_ - 1) ? row[d + 1] : 0.f;
            float conv = k0 * xm + k1 * xc + k2 * xp;
            float bn = (conv - rm) * inv + bb;
            float av = fmaxf(bn, 0.f);
            g_a[ch * D_ + d] = av;
            s += av;
        }
        #pragma unroll
        for (int o = 16; o; o >>= 1) s += __shfl_down_sync(0xffffffffu, s, o);
        if (lane == 0) b1s[ch] = s * (1.f / 196.f);
    }
    __syncthreads();

    if (tid < NCH_) {
        const float bi = b1s[tid];
        float mx = -1e30f, mn = 1e30f;
        int cnt_nonpos = 0, rank = 0;
        #pragma unroll 8
        for (int j = 0; j < NCH_; j++) {
            float bj = b1s[j];
            mx = fmaxf(mx, bj); mn = fminf(mn, bj);
            if (bj <= 0.f) cnt_nonpos++;
            if (bj < bi || (bj == bi && j < tid)) rank++;
        }
        int middle = (mx < 0.f || mn > 0.f) ? 32 : (mx > 0.f ? cnt_nonpos : 0);
        float b2;
        if (rank < middle) {
            float ls = (float)middle;
            b2 = bi - 1.f / (1.f + powf(ls, bi));
        } else {
            float le = (float)(NCH_ - middle);
            b2 = bi + 1.f / (1.f + powf(le, -bi));
        }
        b2s[tid] = b2;
    }
    __syncthreads();

    if (tid < 12) {
        float s = 0.f;
        #pragma unroll 8
        for (int i = 0; i < NCH_; i++) s += b2s[i] * fc_w1[i * 12 + tid];
        hid[tid] = fmaxf(s, 0.f);
    }
    __syncthreads();
    if (tid < NCH_) {
        float s = 0.f;
        #pragma unroll
        for (int j = 0; j < 12; j++) s += hid[j] * fc_w2[j * NCH_ + tid];
        cs[tid] = 1.f / (1.f + expf(-s));
    }
    __syncthreads();

    float* xatt = (float*)g_xatt4;
    for (int idx = tid; idx < NCH_ * D_; idx += 256)
        xatt[idx] = g_a[idx] * cs[idx / D_];
    for (int d = tid; d < D_; d += 256)
        xatt[NCH_ * D_ + d] = tokens[d];
}

// ============================================================
// K2: QKV GEMM, 4-row tile. grid (3, 17), 128 threads.
// ============================================================
__global__ __launch_bounds__(128) void k_qkv(const float4* __restrict__ w4)
{
    __shared__ float hs[4 * D_];
    const int tid  = threadIdx.x;
    const int base = blockIdx.y * 4;

    for (int idx = tid; idx < 4 * D_; idx += 128) {
        int r = idx / D_, c = idx - r * D_;
        int row = base + r;
        hs[idx] = (row < SEQ_) ? g_h1[row * D_ + c] : 0.f;
    }
    __syncthreads();

    const int g = blockIdx.x * 128 + tid;   // < 384
    float4 acc[4];
    #pragma unroll
    for (int r = 0; r < 4; r++) acc[r] = make_float4(0.f, 0.f, 0.f, 0.f);

    const float4* W = w4 + g;
    #pragma unroll 4
    for (int k = 0; k < D_; k++) {
        float4 w = W[k * NG_QKV];
        fma4(acc[0], hs[k], w);
        fma4(acc[1], hs[D_ + k], w);
        fma4(acc[2], hs[2 * D_ + k], w);
        fma4(acc[3], hs[3 * D_ + k], w);
    }
    if (g < 128) {  // q slice: pre-scale by DH^-0.5
        #pragma unroll
        for (int r = 0; r < 4; r++) {
            acc[r].x *= 0.125f; acc[r].y *= 0.125f;
            acc[r].z *= 0.125f; acc[r].w *= 0.125f;
        }
    }
    #pragma unroll
    for (int r = 0; r < 4; r++) {
        int row = base + r;
        if (row < SEQ_) g_qkv4[row * NG_QKV + g] = acc[r];
    }
}

// ============================================================
// K3: attention. grid (65, 8). 128 threads.
// ============================================================
__global__ __launch_bounds__(128) void k_attn()
{
    const int n = blockIdx.x, hh = blockIdx.y;
    const int tid = threadIdx.x;
    const float* qkv = (const float*)g_qkv4;

    __shared__ float q[DH_];
    __shared__ float sc[96];
    __shared__ float smax, sinv;

    if (tid < DH_) q[tid] = qkv[n * 1536 + hh * DH_ + tid];
    if (tid >= SEQ_ && tid < 96) sc[tid] = -1e30f;
    __syncthreads();

    if (tid < SEQ_) {
        const float4* kr = (const float4*)(qkv + tid * 1536 + INNER_ + hh * DH_);
        float s = 0.f;
        #pragma unroll
        for (int d4 = 0; d4 < 16; d4++) {
            float4 k4 = kr[d4];
            s += q[4*d4] * k4.x + q[4*d4+1] * k4.y + q[4*d4+2] * k4.z + q[4*d4+3] * k4.w;
        }
        sc[tid] = s;
    }
    __syncthreads();
    if (tid < 32) {
        float m = fmaxf(fmaxf(sc[tid], sc[tid + 32]), sc[tid + 64]);
        #pragma unroll
        for (int o = 16; o; o >>= 1) m = fmaxf(m, __shfl_down_sync(0xffffffffu, m, o));
        if (tid == 0) smax = m;
    }
    __syncthreads();
    if (tid < SEQ_) sc[tid] = expf(sc[tid] - smax);
    else if (tid < 96) sc[tid] = 0.f;
    __syncthreads();
    if (tid < 32) {
        float s = sc[tid] + sc[tid + 32] + sc[tid + 64];
        #pragma unroll
        for (int o = 16; o; o >>= 1) s += __shfl_down_sync(0xffffffffu, s, o);
        if (tid == 0) sinv = 1.f / s;
    }
    __syncthreads();
    if (tid < DH_) {
        const float* vb = qkv + 2 * INNER_ + hh * DH_ + tid;
        float acc = 0.f;
        #pragma unroll 5
        for (int m = 0; m < SEQ_; m++) acc += sc[m] * vb[m * 1536];
        ((float*)g_o4)[n * INNER_ + hh * DH_ + tid] = acc * sinv;
    }
}

// ============================================================
// K4: out-proj + residuals + LN2. grid 17, 196 threads.
// 4 rows/block, K=512 split into 4 slices of 128.
// ============================================================
__global__ __launch_bounds__(196) void k_outproj(
    const float* __restrict__ x,
    const float4* __restrict__ wout4, const float4* __restrict__ bout4,
    const float4* __restrict__ ln2g4, const float4* __restrict__ ln2b4)
{
    __shared__ float4 os4[4 * 128];
    __shared__ float4 red[4 * NG_D * 4];
    __shared__ float p1[4][NG_D], p2[4][NG_D];
    __shared__ float mrow[4], rrow[4];
    float* os = (float*)os4;

    const int tid  = threadIdx.x;
    const int base = blockIdx.x * 4;
    const int s = tid / NG_D, g = tid - s * NG_D;

    for (int idx = tid; idx < 4 * 128; idx += 196) {
        int r = idx >> 7, c = idx & 127;
        int row = base + r;
        os4[idx] = (row < SEQ_) ? g_o4[row * 128 + c] : make_float4(0.f, 0.f, 0.f, 0.f);
    }
    __syncthreads();

    float4 acc[4];
    #pragma unroll
    for (int r = 0; r < 4; r++) acc[r] = make_float4(0.f, 0.f, 0.f, 0.f);

    const float4* W = wout4 + (s * 128) * NG_D + g;
    const float* hb = os + s * 128;
    #pragma unroll 8
    for (int k = 0; k < 128; k++) {
        float4 w = W[k * NG_D];
        fma4(acc[0], hb[k], w);
        fma4(acc[1], hb[512 + k], w);
        fma4(acc[2], hb[1024 + k], w);
        fma4(acc[3], hb[1536 + k], w);
    }
    #pragma unroll
    for (int r = 0; r < 4; r++) red[(s * NG_D + g) * 4 + r] = acc[r];
    __syncthreads();

    float4 val[4];
    if (s == 0) {
        float4 bo = bout4[g];
        #pragma unroll
        for (int r = 0; r < 4; r++) {
            float4 v = acc[r];
            #pragma unroll
            for (int ss = 1; ss < 4; ss++) {
                float4 t = red[(ss * NG_D + g) * 4 + r];
                v.x += t.x; v.y += t.y; v.z += t.z; v.w += t.w;
            }
            int row = base + r;
            float4 xv = make_float4(0.f, 0.f, 0.f, 0.f), xa = xv;
            if (row < SEQ_) {
                xv = ((const float4*)x)[row * NG_D + g];
                xa = g_xatt4[row * NG_D + g];
            }
            v.x += bo.x + xv.x + xa.x;
            v.y += bo.y + xv.y + xa.y;
            v.z += bo.z + xv.z + xa.z;
            v.w += bo.w + xv.w + xa.w;
            val[r] = v;
            if (row < SEQ_) g_x2_4[row * NG_D + g] = v;
            p1[r][g] = v.x + v.y + v.z + v.w;
            p2[r][g] = v.x*v.x + v.y*v.y + v.z*v.z + v.w*v.w;
        }
    }
    __syncthreads();
    if (tid < 4) {
        float t1 = 0.f, t2 = 0.f;
        #pragma unroll 7
        for (int i = 0; i < NG_D; i++) { t1 += p1[tid][i]; t2 += p2[tid][i]; }
        float mean = t1 * (1.f / 196.f);
        float var  = t2 * (1.f / 196.f) - mean * mean;
        mrow[tid] = mean; rrow[tid] = rsqrtf(var + 1e-5f);
    }
    __syncthreads();
    if (s == 0) {
        float4 gg = ln2g4[g], bb = ln2b4[g];
        #pragma unroll
        for (int r = 0; r < 4; r++) {
            int row = base + r;
            if (row < SEQ_) {
                float m = mrow[r], rs = rrow[r];
                float4 v = val[r], h;
                h.x = (v.x - m) * rs * gg.x + bb.x;
                h.y = (v.y - m) * rs * gg.y + bb.y;
                h.z = (v.z - m) * rs * gg.z + bb.z;
                h.w = (v.w - m) * rs * gg.w + bb.w;
                g_h2_4[row * NG_D + g] = h;
            }
        }
    }
}

// ============================================================
// K5: FF1 + exact GELU. grid (2, 17), 128 threads.
// ============================================================
__device__ __forceinline__ float gelu_exact(float v) {
    return 0.5f * v * (1.f + erff(v * 0.70710678118654752f));
}

__global__ __launch_bounds__(128) void k_ff1(
    const float4* __restrict__ ffw1_4, const float4* __restrict__ ffb1_4)
{
    __shared__ float4 hs4[4 * NG_D];
    float* hs = (float*)hs4;
    const int tid  = threadIdx.x;
    const int base = blockIdx.y * 4;

    for (int idx = tid; idx < 4 * NG_D; idx += 128) {
        int r = idx / NG_D, c = idx - r * NG_D;
        int row = base + r;
        hs4[idx] = (row < SEQ_) ? g_h2_4[row * NG_D + c] : make_float4(0.f, 0.f, 0.f, 0.f);
    }
    __syncthreads();

    const int g = blockIdx.x * 128 + tid;   // < 256, valid < 196
    if (g >= NG_MLP) return;

    float4 acc[4];
    #pragma unroll
    for (int r = 0; r < 4; r++) acc[r] = make_float4(0.f, 0.f, 0.f, 0.f);

    const float4* W = ffw1_4 + g;
    #pragma unroll 4
    for (int k = 0; k < D_; k++) {
        float4 w = W[k * NG_MLP];
        fma4(acc[0], hs[k], w);
        fma4(acc[1], hs[D_ + k], w);
        fma4(acc[2], hs[2 * D_ + k], w);
        fma4(acc[3], hs[3 * D_ + k], w);
    }
    float4 fb = ffb1_4[g];
    #pragma unroll
    for (int r = 0; r < 4; r++) {
        int row = base + r;
        if (row < SEQ_) {
            float4 t;
            t.x = gelu_exact(acc[r].x + fb.x);
            t.y = gelu_exact(acc[r].y + fb.y);
            t.z = gelu_exact(acc[r].z + fb.z);
            t.w = gelu_exact(acc[r].w + fb.w);
            g_t4[row * NG_MLP + g] = t;
        }
    }
}

// ============================================================
// K6: FF2 + residual -> out. grid 17, 196 threads.
// K=784 split into 4 slices of 196.
// ============================================================
__global__ __launch_bounds__(196) void k_ff2(
    const float4* __restrict__ ffw2_4, const float4* __restrict__ ffb2_4,
    float4* __restrict__ out4)
{
    __shared__ float4 ts4[4 * NG_MLP];
    __shared__ float4 red[4 * NG_D * 4];
    float* ts = (float*)ts4;

    const int tid  = threadIdx.x;
    const int base = blockIdx.x * 4;
    const int s = tid / NG_D, g = tid - s * NG_D;

    for (int idx = tid; idx < 4 * NG_MLP; idx += 196) {
        int r = idx / NG_MLP, c = idx - r * NG_MLP;
        int row = base + r;
        ts4[idx] = (row < SEQ_) ? g_t4[row * NG_MLP + c] : make_float4(0.f, 0.f, 0.f, 0.f);
    }
    __syncthreads();

    float4 acc[4];
    #pragma unroll
    for (int r = 0; r < 4; r++) acc[r] = make_float4(0.f, 0.f, 0.f, 0.f);

    const float4* W = ffw2_4 + (s * 196) * NG_D + g;
    const float* hb = ts + s * 196;
    #pragma unroll 4
    for (int k = 0; k < 196; k++) {
        float4 w = W[k * NG_D];
        fma4(acc[0], hb[k], w);
        fma4(acc[1], hb[MLP_ + k], w);
        fma4(acc[2], hb[2 * MLP_ + k], w);
        fma4(acc[3], hb[3 * MLP_ + k], w);
    }
    #pragma unroll
    for (int r = 0; r < 4; r++) red[(s * NG_D + g) * 4 + r] = acc[r];
    __syncthreads();

    if (s == 0) {
        float4 fb = ffb2_4[g];
        #pragma unroll
        for (int r = 0; r < 4; r++) {
            int row = base + r;
            if (row >= SEQ_) continue;
            float4 v = acc[r];
            #pragma unroll
            for (int ss = 1; ss < 4; ss++) {
                float4 t = red[(ss * NG_D + g) * 4 + r];
                v.x += t.x; v.y += t.y; v.z += t.z; v.w += t.w;
            }
            float4 x2 = g_x2_4[row * NG_D + g];
            v.x += fb.x + x2.x; v.y += fb.y + x2.y;
            v.z += fb.z + x2.z; v.w += fb.w + x2.w;
            out4[row * NG_D + g] = v;
        }
    }
}

// ============================================================
extern "C" void kernel_launch(void* const* d_in, const int* in_sizes, int n_in,
                              void* d_out, int out_size)
{
    const float* x      = (const float*)d_in[0];
    const float* tokens = (const float*)d_in[1];
    const float* x_pe   = (const float*)d_in[2];
    const float* conv_k = (const float*)d_in[3];
    const float* bn_g   = (const float*)d_in[4];
    const float* bn_b   = (const float*)d_in[5];
    const float* bn_rm  = (const float*)d_in[6];
    const float* bn_rv  = (const float*)d_in[7];
    const float* fc_w1  = (const float*)d_in[8];
    const float* fc_w2  = (const float*)d_in[9];
    const float* ln1_g  = (const float*)d_in[10];
    const float* ln1_b  = (const float*)d_in[11];
    const float* ln2_g  = (const float*)d_in[12];
    const float* ln2_b  = (const float*)d_in[13];
    const float* w_qkv  = (const float*)d_in[14];
    const float* w_out  = (const float*)d_in[15];
    const float* b_out  = (const float*)d_in[16];
    const float* ff_w1  = (const float*)d_in[17];
    const float* ff_b1  = (const float*)d_in[18];
    const float* ff_w2  = (const float*)d_in[19];
    const float* ff_b2  = (const float*)d_in[20];

    k_pre<<<SEQ_ + 1, 256>>>(x, tokens, x_pe, conv_k, bn_g, bn_b, bn_rm, bn_rv,
                             fc_w1, fc_w2, ln1_g, ln1_b);
    k_qkv<<<dim3(3, 17), 128>>>((const float4*)w_qkv);
    k_attn<<<dim3(SEQ_, H_), 128>>>();
    k_outproj<<<17, 196>>>(x, (const float4*)w_out, (const float4*)b_out,
                           (const float4*)ln2_g, (const float4*)ln2_b);
    k_ff1<<<dim3(2, 17), 128>>>((const float4*)ff_w1, (const float4*)ff_b1);
    k_ff2<<<17, 196>>>((const float4*)ff_w2, (const float4*)ff_b2, (float4*)d_out);
}

// round 5
// speedup vs baseline: 1.5847x; 1.5847x over previous
#include <cuda_runtime.h>
#include <math.h>

#define D_     196
#define NCH_   64
#define H_     8
#define DH_    64
#define INNER_ 512
#define MLP_   784
#define SEQ_   65

#define NG_QKV 384   // 1536/4
#define NG_D   49    // 196/4
#define NG_MLP 196   // 784/4

// ---- scratch (__device__ globals; no allocations allowed) ----
__device__ float  g_a[NCH_ * D_];
__device__ float4 g_xatt4[SEQ_ * NG_D];
__device__ float4 g_qkv4[SEQ_ * NG_QKV];    // q(pre-scaled)|k|v
__device__ float4 g_o4[SEQ_ * 128];         // attention output
__device__ float4 g_x2_4[SEQ_ * NG_D];      // after attn residuals
__device__ float4 g_h2_4[SEQ_ * NG_D];      // LN2(x2)
__device__ float4 g_t4[SEQ_ * NG_MLP];      // gelu(ff1)

__device__ __forceinline__ void fma4(float4& a, float h, const float4& w) {
    a.x += h * w.x; a.y += h * w.y; a.z += h * w.z; a.w += h * w.w;
}
__device__ __forceinline__ void add4(float4& a, const float4& b) {
    a.x += b.x; a.y += b.y; a.z += b.z; a.w += b.w;
}

// ============================================================
// K1: fused LN1+QKV GEMM (4-row tiles, 2 K-slices) + gating block.
// grid (3, 18), 256 threads.
//   by < 17 : rows base=by*4; col groups g = bx*128 + (tid&127),
//             K slice s = tid>>7 (98 each), smem reduce.
//   by == 17, bx == 0 : channel gating -> g_xatt4.
// ============================================================
__global__ __launch_bounds__(256) void k_qkv_pre(
    const float* __restrict__ x, const float* __restrict__ tokens,
    const float* __restrict__ x_pe, const float* __restrict__ conv_k,
    const float* __restrict__ bn_g, const float* __restrict__ bn_b,
    const float* __restrict__ bn_rm, const float* __restrict__ bn_rv,
    const float* __restrict__ fc_w1, const float* __restrict__ fc_w2,
    const float* __restrict__ ln1_g, const float* __restrict__ ln1_b,
    const float4* __restrict__ w4)
{
    const int tid = threadIdx.x;

    if (blockIdx.y == 17) {
        if (blockIdx.x != 0) return;
        // ---------------- gating (one block) ----------------
        __shared__ float b1s[NCH_];
        __shared__ float b2s[NCH_];
        __shared__ float hid[12];
        __shared__ float cs[NCH_];

        const int warp = tid >> 5, lane = tid & 31;
        const float k0 = conv_k[3], k1 = conv_k[4], k2 = conv_k[5];
        const float rm  = bn_rm[0];
        const float inv = rsqrtf(bn_rv[0] + 1e-5f) * bn_g[0];
        const float bb  = bn_b[0];

        for (int ch = warp; ch < NCH_; ch += 8) {
            const float* row = x_pe + ch * D_;
            float s = 0.f;
            for (int d = lane; d < D_; d += 32) {
                float xm = (d > 0)      ? row[d - 1] : 0.f;
                float xc = row[d];
                float xp = (d < D_ - 1) ? row[d + 1] : 0.f;
                float conv = k0 * xm + k1 * xc + k2 * xp;
                float bn = (conv - rm) * inv + bb;
                float av = fmaxf(bn, 0.f);
                g_a[ch * D_ + d] = av;
                s += av;
            }
            #pragma unroll
            for (int o = 16; o; o >>= 1) s += __shfl_down_sync(0xffffffffu, s, o);
            if (lane == 0) b1s[ch] = s * (1.f / 196.f);
        }
        __syncthreads();

        if (tid < NCH_) {
            const float bi = b1s[tid];
            float mx = -1e30f, mn = 1e30f;
            int cnt_nonpos = 0, rank = 0;
            #pragma unroll 8
            for (int j = 0; j < NCH_; j++) {
                float bj = b1s[j];
                mx = fmaxf(mx, bj); mn = fminf(mn, bj);
                if (bj <= 0.f) cnt_nonpos++;
                if (bj < bi || (bj == bi && j < tid)) rank++;
            }
            int middle = (mx < 0.f || mn > 0.f) ? 32 : (mx > 0.f ? cnt_nonpos : 0);
            float b2;
            if (rank < middle) {
                float ls = (float)middle;
                b2 = bi - 1.f / (1.f + powf(ls, bi));
            } else {
                float le = (float)(NCH_ - middle);
                b2 = bi + 1.f / (1.f + powf(le, -bi));
            }
            b2s[tid] = b2;
        }
        __syncthreads();
        if (tid < 12) {
            float s = 0.f;
            #pragma unroll 8
            for (int i = 0; i < NCH_; i++) s += b2s[i] * fc_w1[i * 12 + tid];
            hid[tid] = fmaxf(s, 0.f);
        }
        __syncthreads();
        if (tid < NCH_) {
            float s = 0.f;
            #pragma unroll
            for (int j = 0; j < 12; j++) s += hid[j] * fc_w2[j * NCH_ + tid];
            cs[tid] = 1.f / (1.f + expf(-s));
        }
        __syncthreads();
        float* xatt = (float*)g_xatt4;
        for (int idx = tid; idx < NCH_ * D_; idx += 256)
            xatt[idx] = g_a[idx] * cs[idx / D_];
        for (int d = tid; d < D_; d += 256)
            xatt[NCH_ * D_ + d] = tokens[d];
        return;
    }

    // ---------------- LN1 + QKV ----------------
    __shared__ float hs[4 * D_];
    __shared__ float mrow[4], rrow[4];
    __shared__ float4 red[128 * 4];

    const int base = blockIdx.y * 4;

    for (int idx = tid; idx < 4 * D_; idx += 256) {
        int r = idx / D_, c = idx - r * D_;
        int row = base + r;
        hs[idx] = (row < SEQ_) ? x[row * D_ + c] : 0.f;
    }
    __syncthreads();

    const int warp = tid >> 5, lane = tid & 31;
    if (warp < 4) {
        float s1 = 0.f, s2 = 0.f;
        #pragma unroll
        for (int i = 0; i < 7; i++) {
            int c = lane + 32 * i;
            if (c < D_) { float v = hs[warp * D_ + c]; s1 += v; s2 += v * v; }
        }
        #pragma unroll
        for (int o = 16; o; o >>= 1) {
            s1 += __shfl_down_sync(0xffffffffu, s1, o);
            s2 += __shfl_down_sync(0xffffffffu, s2, o);
        }
        if (lane == 0) {
            float mean = s1 * (1.f / 196.f);
            float var  = s2 * (1.f / 196.f) - mean * mean;
            mrow[warp] = mean; rrow[warp] = rsqrtf(var + 1e-5f);
        }
    }
    __syncthreads();
    for (int idx = tid; idx < 4 * D_; idx += 256) {
        int r = idx / D_, c = idx - r * D_;
        hs[idx] = (hs[idx] - mrow[r]) * rrow[r] * ln1_g[c] + ln1_b[c];
    }
    __syncthreads();

    const int gl = tid & 127;                  // local col group
    const int g  = blockIdx.x * 128 + gl;      // global col group < 384
    const int s  = tid >> 7;                   // K slice 0/1
    float4 acc[4];
    #pragma unroll
    for (int r = 0; r < 4; r++) acc[r] = make_float4(0.f, 0.f, 0.f, 0.f);

    const int kb = s * 98;
    const float4* W = w4 + kb * NG_QKV + g;
    #pragma unroll 7
    for (int k = 0; k < 98; k++) {
        float4 w = W[k * NG_QKV];
        fma4(acc[0], hs[kb + k], w);
        fma4(acc[1], hs[D_ + kb + k], w);
        fma4(acc[2], hs[2 * D_ + kb + k], w);
        fma4(acc[3], hs[3 * D_ + kb + k], w);
    }
    if (s == 1) {
        #pragma unroll
        for (int r = 0; r < 4; r++) red[gl * 4 + r] = acc[r];
    }
    __syncthreads();
    if (s == 0) {
        float sc = (g < 128) ? 0.125f : 1.f;   // q pre-scale DH^-0.5
        #pragma unroll
        for (int r = 0; r < 4; r++) {
            float4 v = acc[r];
            add4(v, red[gl * 4 + r]);
            v.x *= sc; v.y *= sc; v.z *= sc; v.w *= sc;
            int row = base + r;
            if (row < SEQ_) g_qkv4[row * NG_QKV + g] = v;
        }
    }
}

// ============================================================
// K2: attention. grid (65, 8). 128 threads. V-tile in smem.
// ============================================================
__global__ __launch_bounds__(128) void k_attn()
{
    const int n = blockIdx.x, hh = blockIdx.y;
    const int tid = threadIdx.x;
    const float* qkv = (const float*)g_qkv4;

    __shared__ float4 vsm4[SEQ_ * 16];   // 65 x 64 V values
    __shared__ float q[DH_];
    __shared__ float sc[96];
    __shared__ float smax, sinv;

    // preload V head tile (one parallel latency wave)
    for (int idx = tid; idx < SEQ_ * 16; idx += 128) {
        int row = idx >> 4, c = idx & 15;
        vsm4[idx] = ((const float4*)(qkv + row * 1536 + 2 * INNER_ + hh * DH_))[c];
    }
    if (tid < DH_) q[tid] = qkv[n * 1536 + hh * DH_ + tid];
    if (tid >= SEQ_ && tid < 96) sc[tid] = -1e30f;
    __syncthreads();

    if (tid < SEQ_) {
        const float4* kr = (const float4*)(qkv + tid * 1536 + INNER_ + hh * DH_);
        float s = 0.f;
        #pragma unroll
        for (int d4 = 0; d4 < 16; d4++) {
            float4 k4 = kr[d4];
            s += q[4*d4] * k4.x + q[4*d4+1] * k4.y + q[4*d4+2] * k4.z + q[4*d4+3] * k4.w;
        }
        sc[tid] = s;
    }
    __syncthreads();
    if (tid < 32) {
        float m = fmaxf(fmaxf(sc[tid], sc[tid + 32]), sc[tid + 64]);
        #pragma unroll
        for (int o = 16; o; o >>= 1) m = fmaxf(m, __shfl_down_sync(0xffffffffu, m, o));
        if (tid == 0) smax = m;
    }
    __syncthreads();
    if (tid < SEQ_) sc[tid] = expf(sc[tid] - smax);
    else if (tid < 96) sc[tid] = 0.f;
    __syncthreads();
    if (tid < 32) {
        float s = sc[tid] + sc[tid + 32] + sc[tid + 64];
        #pragma unroll
        for (int o = 16; o; o >>= 1) s += __shfl_down_sync(0xffffffffu, s, o);
        if (tid == 0) sinv = 1.f / s;
    }
    __syncthreads();
    if (tid < DH_) {
        const float* vs = (const float*)vsm4;
        float acc = 0.f;
        #pragma unroll 5
        for (int m = 0; m < SEQ_; m++) acc += sc[m] * vs[m * DH_ + tid];
        ((float*)g_o4)[n * INNER_ + hh * DH_ + tid] = acc * sinv;
    }
}

// ============================================================
// K3: out-proj + residuals + LN2. grid 17, 392 threads.
// 4 rows/block; K=512 in 8 slices of 64; smem reduce.
// ============================================================
__global__ __launch_bounds__(392) void k_outproj(
    const float* __restrict__ x,
    const float4* __restrict__ wout4, const float4* __restrict__ bout4,
    const float4* __restrict__ ln2g4, const float4* __restrict__ ln2b4)
{
    __shared__ float4 os4[4 * 128];
    __shared__ float4 red[8 * NG_D * 4];
    __shared__ float p1[4][NG_D], p2[4][NG_D];
    __shared__ float mrow[4], rrow[4];
    float* os = (float*)os4;

    const int tid  = threadIdx.x;
    const int base = blockIdx.x * 4;
    const int s = tid / NG_D, g = tid - s * NG_D;   // s<8, g<49

    for (int idx = tid; idx < 4 * 128; idx += 392) {
        int r = idx >> 7, c = idx & 127;
        int row = base + r;
        os4[idx] = (row < SEQ_) ? g_o4[row * 128 + c] : make_float4(0.f, 0.f, 0.f, 0.f);
    }
    __syncthreads();

    float4 acc[4];
    #pragma unroll
    for (int r = 0; r < 4; r++) acc[r] = make_float4(0.f, 0.f, 0.f, 0.f);

    const int kb = s * 64;
    const float4* W = wout4 + kb * NG_D + g;
    const float* hb = os + kb;
    #pragma unroll 8
    for (int k = 0; k < 64; k++) {
        float4 w = W[k * NG_D];
        fma4(acc[0], hb[k], w);
        fma4(acc[1], hb[512 + k], w);
        fma4(acc[2], hb[1024 + k], w);
        fma4(acc[3], hb[1536 + k], w);
    }
    if (s > 0) {
        #pragma unroll
        for (int r = 0; r < 4; r++) red[(s * NG_D + g) * 4 + r] = acc[r];
    }
    __syncthreads();

    float4 val[4];
    if (s == 0) {
        float4 bo = bout4[g];
        #pragma unroll
        for (int r = 0; r < 4; r++) {
            float4 v = acc[r];
            #pragma unroll
            for (int ss = 1; ss < 8; ss++) add4(v, red[(ss * NG_D + g) * 4 + r]);
            int row = base + r;
            float4 xv = make_float4(0.f, 0.f, 0.f, 0.f), xa = xv;
            if (row < SEQ_) {
                xv = ((const float4*)x)[row * NG_D + g];
                xa = g_xatt4[row * NG_D + g];
            }
            v.x += bo.x + xv.x + xa.x;
            v.y += bo.y + xv.y + xa.y;
            v.z += bo.z + xv.z + xa.z;
            v.w += bo.w + xv.w + xa.w;
            val[r] = v;
            if (row < SEQ_) g_x2_4[row * NG_D + g] = v;
            p1[r][g] = v.x + v.y + v.z + v.w;
            p2[r][g] = v.x*v.x + v.y*v.y + v.z*v.z + v.w*v.w;
        }
    }
    __syncthreads();
    if (tid < 4) {
        float t1 = 0.f, t2 = 0.f;
        #pragma unroll 7
        for (int i = 0; i < NG_D; i++) { t1 += p1[tid][i]; t2 += p2[tid][i]; }
        float mean = t1 * (1.f / 196.f);
        float var  = t2 * (1.f / 196.f) - mean * mean;
        mrow[tid] = mean; rrow[tid] = rsqrtf(var + 1e-5f);
    }
    __syncthreads();
    if (s == 0) {
        float4 gg = ln2g4[g], bb = ln2b4[g];
        #pragma unroll
        for (int r = 0; r < 4; r++) {
            int row = base + r;
            if (row < SEQ_) {
                float m = mrow[r], rs = rrow[r];
                float4 v = val[r], h;
                h.x = (v.x - m) * rs * gg.x + bb.x;
                h.y = (v.y - m) * rs * gg.y + bb.y;
                h.z = (v.z - m) * rs * gg.z + bb.z;
                h.w = (v.w - m) * rs * gg.w + bb.w;
                g_h2_4[row * NG_D + g] = h;
            }
        }
    }
}

// ============================================================
// K4: FF1 + exact GELU. grid (4, 17), 98 threads.
// 49 col groups x 2 K-slices of 98.
// ============================================================
__device__ __forceinline__ float gelu_exact(float v) {
    return 0.5f * v * (1.f + erff(v * 0.70710678118654752f));
}

__global__ __launch_bounds__(98) void k_ff1(
    const float4* __restrict__ ffw1_4, const float4* __restrict__ ffb1_4)
{
    __shared__ float hs[4 * D_];
    __shared__ float4 red[NG_D * 4];

    const int tid  = threadIdx.x;
    const int base = blockIdx.y * 4;
    const int s = tid / NG_D, gl = tid - s * NG_D;   // s<2, gl<49
    const int g = blockIdx.x * NG_D + gl;            // < 196

    for (int idx = tid; idx < 4 * NG_D; idx += 98) {
        int r = idx / NG_D, c = idx - r * NG_D;
        int row = base + r;
        ((float4*)hs)[r * NG_D + c] =
            (row < SEQ_) ? g_h2_4[row * NG_D + c] : make_float4(0.f, 0.f, 0.f, 0.f);
    }
    __syncthreads();

    float4 acc[4];
    #pragma unroll
    for (int r = 0; r < 4; r++) acc[r] = make_float4(0.f, 0.f, 0.f, 0.f);

    const int kb = s * 98;
    const float4* W = ffw1_4 + kb * NG_MLP + g;
    #pragma unroll 7
    for (int k = 0; k < 98; k++) {
        float4 w = W[k * NG_MLP];
        fma4(acc[0], hs[kb + k], w);
        fma4(acc[1], hs[D_ + kb + k], w);
        fma4(acc[2], hs[2 * D_ + kb + k], w);
        fma4(acc[3], hs[3 * D_ + kb + k], w);
    }
    if (s == 1) {
        #pragma unroll
        for (int r = 0; r < 4; r++) red[gl * 4 + r] = acc[r];
    }
    __syncthreads();
    if (s == 0) {
        float4 fb = ffb1_4[g];
        #pragma unroll
        for (int r = 0; r < 4; r++) {
            int row = base + r;
            if (row < SEQ_) {
                float4 v = acc[r];
                add4(v, red[gl * 4 + r]);
                float4 t;
                t.x = gelu_exact(v.x + fb.x);
                t.y = gelu_exact(v.y + fb.y);
                t.z = gelu_exact(v.z + fb.z);
                t.w = gelu_exact(v.w + fb.w);
                g_t4[row * NG_MLP + g] = t;
            }
        }
    }
}

// ============================================================
// K5: FF2 + residual -> out. grid 17, 392 threads.
// 49 col groups x 8 K-slices of 98.
// ============================================================
__global__ __launch_bounds__(392) void k_ff2(
    const float4* __restrict__ ffw2_4, const float4* __restrict__ ffb2_4,
    float4* __restrict__ out4)
{
    __shared__ float ts[4 * MLP_];
    __shared__ float4 red[8 * NG_D * 4];

    const int tid  = threadIdx.x;
    const int base = blockIdx.x * 4;
    const int s = tid / NG_D, g = tid - s * NG_D;   // s<8, g<49

    for (int idx = tid; idx < 4 * NG_MLP; idx += 392) {
        int r = idx / NG_MLP, c = idx - r * NG_MLP;
        int row = base + r;
        ((float4*)ts)[r * NG_MLP + c] =
            (row < SEQ_) ? g_t4[row * NG_MLP + c] : make_float4(0.f, 0.f, 0.f, 0.f);
    }
    __syncthreads();

    float4 acc[4];
    #pragma unroll
    for (int r = 0; r < 4; r++) acc[r] = make_float4(0.f, 0.f, 0.f, 0.f);

    const int kb = s * 98;
    const float4* W = ffw2_4 + kb * NG_D + g;
    const float* hb = ts + kb;
    #pragma unroll 7
    for (int k = 0; k < 98; k++) {
        float4 w = W[k * NG_D];
        fma4(acc[0], hb[k], w);
        fma4(acc[1], hb[MLP_ + k], w);
        fma4(acc[2], hb[2 * MLP_ + k], w);
        fma4(acc[3], hb[3 * MLP_ + k], w);
    }
    if (s > 0) {
        #pragma unroll
        for (int r = 0; r < 4; r++) red[(s * NG_D + g) * 4 + r] = acc[r];
    }
    __syncthreads();
    if (s == 0) {
        float4 fb = ffb2_4[g];
        #pragma unroll
        for (int r = 0; r < 4; r++) {
            int row = base + r;
            if (row >= SEQ_) continue;
            float4 v = acc[r];
            #pragma unroll
            for (int ss = 1; ss < 8; ss++) add4(v, red[(ss * NG_D + g) * 4 + r]);
            float4 x2 = g_x2_4[row * NG_D + g];
            v.x += fb.x + x2.x; v.y += fb.y + x2.y;
            v.z += fb.z + x2.z; v.w += fb.w + x2.w;
            out4[row * NG_D + g] = v;
        }
    }
}

// ============================================================
extern "C" void kernel_launch(void* const* d_in, const int* in_sizes, int n_in,
                              void* d_out, int out_size)
{
    const float* x      = (const float*)d_in[0];
    const float* tokens = (const float*)d_in[1];
    const float* x_pe   = (const float*)d_in[2];
    const float* conv_k = (const float*)d_in[3];
    const float* bn_g   = (const float*)d_in[4];
    const float* bn_b   = (const float*)d_in[5];
    const float* bn_rm  = (const float*)d_in[6];
    const float* bn_rv  = (const float*)d_in[7];
    const float* fc_w1  = (const float*)d_in[8];
    const float* fc_w2  = (const float*)d_in[9];
    const float* ln1_g  = (const float*)d_in[10];
    const float* ln1_b  = (const float*)d_in[11];
    const float* ln2_g  = (const float*)d_in[12];
    const float* ln2_b  = (const float*)d_in[13];
    const float* w_qkv  = (const float*)d_in[14];
    const float* w_out  = (const float*)d_in[15];
    const float* b_out  = (const float*)d_in[16];
    const float* ff_w1  = (const float*)d_in[17];
    const float* ff_b1  = (const float*)d_in[18];
    const float* ff_w2  = (const float*)d_in[19];
    const float* ff_b2  = (const float*)d_in[20];

    k_qkv_pre<<<dim3(3, 18), 256>>>(x, tokens, x_pe, conv_k, bn_g, bn_b, bn_rm, bn_rv,
                                    fc_w1, fc_w2, ln1_g, ln1_b, (const float4*)w_qkv);
    k_attn<<<dim3(SEQ_, H_), 128>>>();
    k_outproj<<<17, 392>>>(x, (const float4*)w_out, (const float4*)b_out,
                           (const float4*)ln2_g, (const float4*)ln2_b);
    k_ff1<<<dim3(4, 17), 98>>>((const float4*)ff_w1, (const float4*)ff_b1);
    k_ff2<<<17, 392>>>((const float4*)ff_w2, (const float4*)ff_b2, (float4*)d_out);
}

// round 6
// speedup vs baseline: 1.8596x; 1.1735x over previous
#include <cuda_runtime.h>
#include <math.h>

#define D_     196
#define NCH_   64
#define H_     8
#define DH_    64
#define INNER_ 512
#define MLP_   784
#define SEQ_   65
#define NG_QKV 384   // 1536/4
#define NG_D   49    // 196/4
#define NG_MLP 196   // 784/4
#define GRID_  68
#define NT_    512

// ---- scratch (__device__ globals; no allocations allowed) ----
__device__ float  g_a[NCH_ * D_];
__device__ float4 g_xatt4[SEQ_ * NG_D];
__device__ float4 g_qkv4[SEQ_ * NG_QKV];    // q(pre-scaled)|k|v
__device__ float4 g_o4[SEQ_ * 128];         // attention output
__device__ float4 g_x2_4[SEQ_ * NG_D];      // after attn residuals
__device__ float4 g_h2_4[SEQ_ * NG_D];      // LN2(x2)
__device__ float4 g_t4[SEQ_ * NG_MLP];      // gelu(ff1)
__device__ unsigned g_cnt;                  // barrier arrival counter (self-resetting)
__device__ unsigned g_gen;                  // barrier generation (monotonic)

__device__ __forceinline__ void fma4(float4& a, float h, const float4& w) {
    a.x += h * w.x; a.y += h * w.y; a.z += h * w.z; a.w += h * w.w;
}
__device__ __forceinline__ void add4(float4& a, const float4& b) {
    a.x += b.x; a.y += b.y; a.z += b.z; a.w += b.w;
}
__device__ __forceinline__ float gelu_exact(float v) {
    return 0.5f * v * (1.f + erff(v * 0.70710678118654752f));
}

// grid-wide barrier: safe because GRID_ (68) < #SMs (148) -> all blocks co-resident.
__device__ __forceinline__ void gsync() {
    __syncthreads();
    if (threadIdx.x == 0) {
        unsigned gen = *(volatile unsigned*)&g_gen;
        __threadfence();
        if (atomicAdd(&g_cnt, 1u) == GRID_ - 1u) {
            atomicExch(&g_cnt, 0u);
            __threadfence();
            atomicAdd(&g_gen, 1u);
        } else {
            while (*(volatile unsigned*)&g_gen == gen) { __nanosleep(64); }
        }
        __threadfence();
    }
    __syncthreads();
}

__global__ __launch_bounds__(NT_, 1) void k_fused(
    const float* __restrict__ x, const float* __restrict__ tokens,
    const float* __restrict__ x_pe, const float* __restrict__ conv_k,
    const float* __restrict__ bn_g, const float* __restrict__ bn_b,
    const float* __restrict__ bn_rm, const float* __restrict__ bn_rv,
    const float* __restrict__ fc_w1, const float* __restrict__ fc_w2,
    const float* __restrict__ ln1_g, const float* __restrict__ ln1_b,
    const float4* __restrict__ wqkv4,
    const float4* __restrict__ wout4, const float4* __restrict__ bout4,
    const float4* __restrict__ ln2g4, const float4* __restrict__ ln2b4,
    const float4* __restrict__ ffw1_4, const float4* __restrict__ ffb1_4,
    const float4* __restrict__ ffw2_4, const float4* __restrict__ ffb2_4,
    float4* __restrict__ out4)
{
    __shared__ __align__(16) char sm[34560];
    const int tid = threadIdx.x;
    const int b   = blockIdx.x;

    // ================= PHASE 0: LN1 + QKV GEMM (blocks 0..50) + gating (51) =================
    if (b < 51) {
        float*  hs   = (float*)sm;                 // 4*196 floats
        float4* red  = (float4*)(sm + 3136);       // 3 slices * 128 gl * 4 rows
        float*  mrow = (float*)(sm + 27712);
        float*  rrow = (float*)(sm + 27728);

        const int tile  = b / 3;
        const int chunk = b - tile * 3;
        const int base  = tile * 4;

        for (int idx = tid; idx < 4 * D_; idx += NT_) {
            int r = idx / D_, c = idx - r * D_;
            int row = base + r;
            hs[idx] = (row < SEQ_) ? x[row * D_ + c] : 0.f;
        }
        __syncthreads();

        const int warp = tid >> 5, lane = tid & 31;
        if (warp < 4) {
            float s1 = 0.f, s2 = 0.f;
            #pragma unroll
            for (int i = 0; i < 7; i++) {
                int c = lane + 32 * i;
                if (c < D_) { float v = hs[warp * D_ + c]; s1 += v; s2 += v * v; }
            }
            #pragma unroll
            for (int o = 16; o; o >>= 1) {
                s1 += __shfl_down_sync(0xffffffffu, s1, o);
                s2 += __shfl_down_sync(0xffffffffu, s2, o);
            }
            if (lane == 0) {
                float mean = s1 * (1.f / 196.f);
                float var  = s2 * (1.f / 196.f) - mean * mean;
                mrow[warp] = mean; rrow[warp] = rsqrtf(var + 1e-5f);
            }
        }
        __syncthreads();
        for (int idx = tid; idx < 4 * D_; idx += NT_) {
            int r = idx / D_, c = idx - r * D_;
            hs[idx] = (hs[idx] - mrow[r]) * rrow[r] * ln1_g[c] + ln1_b[c];
        }
        __syncthreads();

        const int gl = tid & 127;
        const int g  = chunk * 128 + gl;     // < 384
        const int s  = tid >> 7;             // K-slice 0..3, each 49
        float4 acc[4];
        #pragma unroll
        for (int r = 0; r < 4; r++) acc[r] = make_float4(0.f, 0.f, 0.f, 0.f);

        const int kb = s * 49;
        const float4* W = wqkv4 + kb * NG_QKV + g;
        #pragma unroll 7
        for (int k = 0; k < 49; k++) {
            float4 w = W[k * NG_QKV];
            fma4(acc[0], hs[kb + k], w);
            fma4(acc[1], hs[D_ + kb + k], w);
            fma4(acc[2], hs[2 * D_ + kb + k], w);
            fma4(acc[3], hs[3 * D_ + kb + k], w);
        }
        if (s > 0) {
            #pragma unroll
            for (int r = 0; r < 4; r++) red[((s - 1) * 128 + gl) * 4 + r] = acc[r];
        }
        __syncthreads();
        if (s == 0) {
            float sc = (g < 128) ? 0.125f : 1.f;   // q pre-scale DH^-0.5
            #pragma unroll
            for (int r = 0; r < 4; r++) {
                float4 v = acc[r];
                add4(v, red[(0 * 128 + gl) * 4 + r]);
                add4(v, red[(1 * 128 + gl) * 4 + r]);
                add4(v, red[(2 * 128 + gl) * 4 + r]);
                v.x *= sc; v.y *= sc; v.z *= sc; v.w *= sc;
                int row = base + r;
                if (row < SEQ_) g_qkv4[row * NG_QKV + g] = v;
            }
        }
    } else if (b == 51) {
        // ---------------- gating ----------------
        float* b1s = (float*)sm;              // 64
        float* b2s = (float*)(sm + 256);      // 64
        float* hid = (float*)(sm + 512);      // 12
        float* cs  = (float*)(sm + 576);      // 64

        const int warp = tid >> 5, lane = tid & 31;
        const float k0 = conv_k[3], k1 = conv_k[4], k2 = conv_k[5];
        const float rm  = bn_rm[0];
        const float inv = rsqrtf(bn_rv[0] + 1e-5f) * bn_g[0];
        const float bb  = bn_b[0];

        for (int ch = warp; ch < NCH_; ch += 16) {
            const float* row = x_pe + ch * D_;
            float s = 0.f;
            for (int d = lane; d < D_; d += 32) {
                float xm = (d > 0)      ? row[d - 1] : 0.f;
                float xc = row[d];
                float xp = (d < D_ - 1) ? row[d + 1] : 0.f;
                float conv = k0 * xm + k1 * xc + k2 * xp;
                float bn = (conv - rm) * inv + bb;
                float av = fmaxf(bn, 0.f);
                g_a[ch * D_ + d] = av;
                s += av;
            }
            #pragma unroll
            for (int o = 16; o; o >>= 1) s += __shfl_down_sync(0xffffffffu, s, o);
            if (lane == 0) b1s[ch] = s * (1.f / 196.f);
        }
        __syncthreads();

        if (tid < NCH_) {
            const float bi = b1s[tid];
            float mx = -1e30f, mn = 1e30f;
            int cnt_nonpos = 0, rank = 0;
            #pragma unroll 8
            for (int j = 0; j < NCH_; j++) {
                float bj = b1s[j];
                mx = fmaxf(mx, bj); mn = fminf(mn, bj);
                if (bj <= 0.f) cnt_nonpos++;
                if (bj < bi || (bj == bi && j < tid)) rank++;
            }
            int middle = (mx < 0.f || mn > 0.f) ? 32 : (mx > 0.f ? cnt_nonpos : 0);
            float b2;
            if (rank < middle) {
                float ls = (float)middle;
                b2 = bi - 1.f / (1.f + powf(ls, bi));
            } else {
                float le = (float)(NCH_ - middle);
                b2 = bi + 1.f / (1.f + powf(le, -bi));
            }
            b2s[tid] = b2;
        }
        __syncthreads();
        if (tid < 12) {
            float s = 0.f;
            #pragma unroll 8
            for (int i = 0; i < NCH_; i++) s += b2s[i] * fc_w1[i * 12 + tid];
            hid[tid] = fmaxf(s, 0.f);
        }
        __syncthreads();
        if (tid < NCH_) {
            float s = 0.f;
            #pragma unroll
            for (int j = 0; j < 12; j++) s += hid[j] * fc_w2[j * NCH_ + tid];
            cs[tid] = 1.f / (1.f + expf(-s));
        }
        __syncthreads();
        float* xatt = (float*)g_xatt4;
        for (int idx = tid; idx < NCH_ * D_; idx += NT_)
            xatt[idx] = g_a[idx] * cs[idx / D_];
        for (int d = tid; d < D_; d += NT_)
            xatt[NCH_ * D_ + d] = tokens[d];
    }
    gsync();

    // ================= PHASE 1: attention (blocks 0..64, one token row each) =================
    if (b < SEQ_) {
        const float* qkv = (const float*)g_qkv4;
        float* qs   = (float*)sm;             // 8*64
        float* sc   = (float*)(sm + 2048);    // 8 heads * 66 stride
        float* smax = (float*)(sm + 4160);    // 8
        float* sinv = (float*)(sm + 4224);    // 8

        const int h = tid >> 6, d = tid & 63;
        qs[tid] = qkv[b * 1536 + tid];        // q row (pre-scaled), 512 floats
        __syncthreads();

        const float* qh = qs + h * DH_;
        {
            const float4* kr = (const float4*)(qkv + d * 1536 + INNER_ + h * DH_);
            float s = 0.f;
            #pragma unroll
            for (int i = 0; i < 16; i++) {
                float4 k4 = kr[i];
                s += qh[4*i] * k4.x + qh[4*i+1] * k4.y + qh[4*i+2] * k4.z + qh[4*i+3] * k4.w;
            }
            sc[h * 66 + d] = s;
            if (d == 0) {
                const float4* kr2 = (const float4*)(qkv + 64 * 1536 + INNER_ + h * DH_);
                float s2 = 0.f;
                #pragma unroll
                for (int i = 0; i < 16; i++) {
                    float4 k4 = kr2[i];
                    s2 += qh[4*i] * k4.x + qh[4*i+1] * k4.y + qh[4*i+2] * k4.z + qh[4*i+3] * k4.w;
                }
                sc[h * 66 + 64] = s2;
            }
        }
        __syncthreads();
        if (d < 32) {   // warp 2h, fully active
            float m = fmaxf(sc[h * 66 + d], sc[h * 66 + d + 32]);
            if (d == 0) m = fmaxf(m, sc[h * 66 + 64]);
            #pragma unroll
            for (int o = 16; o; o >>= 1) m = fmaxf(m, __shfl_down_sync(0xffffffffu, m, o));
            if (d == 0) smax[h] = m;
        }
        __syncthreads();
        {
            float mx = smax[h];
            sc[h * 66 + d] = expf(sc[h * 66 + d] - mx);
            if (d == 0) sc[h * 66 + 64] = expf(sc[h * 66 + 64] - mx);
        }
        __syncthreads();
        if (d < 32) {
            float s = sc[h * 66 + d] + sc[h * 66 + d + 32];
            if (d == 0) s += sc[h * 66 + 64];
            #pragma unroll
            for (int o = 16; o; o >>= 1) s += __shfl_down_sync(0xffffffffu, s, o);
            if (d == 0) sinv[h] = 1.f / s;
        }
        __syncthreads();
        {
            const float* vb = qkv + 2 * INNER_ + h * DH_ + d;
            const float* p  = sc + h * 66;
            float acc = 0.f;
            #pragma unroll 8
            for (int m = 0; m < SEQ_; m++) acc += p[m] * vb[m * 1536];
            ((float*)g_o4)[b * INNER_ + tid] = acc * sinv[h];
        }
    }
    gsync();

    // ================= PHASE 2: out-proj + residuals + LN2 (blocks 0..16) =================
    if (b < 17) {
        float4* os4  = (float4*)sm;               // 4*128
        float4* red  = (float4*)(sm + 8192);      // 7 slices * 49 * 4
        float*  p1   = (float*)(sm + 30144);      // 4*49
        float*  p2   = (float*)(sm + 30928);      // 4*49
        float*  mrow = (float*)(sm + 31712);
        float*  rrow = (float*)(sm + 31728);
        float*  os   = (float*)os4;

        const int base = b * 4;
        const int s = tid / NG_D, g = tid - s * NG_D;  // s 0..10 (use <8), g<49

        {
            int idx = tid;  // < 512 covers 4*128
            int r = idx >> 7, c = idx & 127;
            int row = base + r;
            os4[idx] = (row < SEQ_) ? g_o4[row * 128 + c] : make_float4(0.f, 0.f, 0.f, 0.f);
        }
        __syncthreads();

        float4 acc[4];
        #pragma unroll
        for (int r = 0; r < 4; r++) acc[r] = make_float4(0.f, 0.f, 0.f, 0.f);

        if (s < 8) {
            const int kb = s * 64;
            const float4* W = wout4 + kb * NG_D + g;
            const float* hb = os + kb;
            #pragma unroll 8
            for (int k = 0; k < 64; k++) {
                float4 w = W[k * NG_D];
                fma4(acc[0], hb[k], w);
                fma4(acc[1], hb[512 + k], w);
                fma4(acc[2], hb[1024 + k], w);
                fma4(acc[3], hb[1536 + k], w);
            }
            if (s > 0) {
                #pragma unroll
                for (int r = 0; r < 4; r++) red[((s - 1) * NG_D + g) * 4 + r] = acc[r];
            }
        }
        __syncthreads();

        float4 val[4];
        if (s == 0) {
            float4 bo = bout4[g];
            #pragma unroll
            for (int r = 0; r < 4; r++) {
                float4 v = acc[r];
                #pragma unroll
                for (int ss = 0; ss < 7; ss++) add4(v, red[(ss * NG_D + g) * 4 + r]);
                int row = base + r;
                float4 xv = make_float4(0.f, 0.f, 0.f, 0.f), xa = xv;
                if (row < SEQ_) {
                    xv = ((const float4*)x)[row * NG_D + g];
                    xa = g_xatt4[row * NG_D + g];
                }
                v.x += bo.x + xv.x + xa.x;
                v.y += bo.y + xv.y + xa.y;
                v.z += bo.z + xv.z + xa.z;
                v.w += bo.w + xv.w + xa.w;
                val[r] = v;
                if (row < SEQ_) g_x2_4[row * NG_D + g] = v;
                p1[r * NG_D + g] = v.x + v.y + v.z + v.w;
                p2[r * NG_D + g] = v.x*v.x + v.y*v.y + v.z*v.z + v.w*v.w;
            }
        }
        __syncthreads();
        if (tid < 4) {
            float t1 = 0.f, t2 = 0.f;
            #pragma unroll 7
            for (int i = 0; i < NG_D; i++) { t1 += p1[tid * NG_D + i]; t2 += p2[tid * NG_D + i]; }
            float mean = t1 * (1.f / 196.f);
            float var  = t2 * (1.f / 196.f) - mean * mean;
            mrow[tid] = mean; rrow[tid] = rsqrtf(var + 1e-5f);
        }
        __syncthreads();
        if (s == 0) {
            float4 gg = ln2g4[g], bb = ln2b4[g];
            #pragma unroll
            for (int r = 0; r < 4; r++) {
                int row = base + r;
                if (row < SEQ_) {
                    float m = mrow[r], rs = rrow[r];
                    float4 v = val[r], h;
                    h.x = (v.x - m) * rs * gg.x + bb.x;
                    h.y = (v.y - m) * rs * gg.y + bb.y;
                    h.z = (v.z - m) * rs * gg.z + bb.z;
                    h.w = (v.w - m) * rs * gg.w + bb.w;
                    g_h2_4[row * NG_D + g] = h;
                }
            }
        }
    }
    gsync();

    // ================= PHASE 3: FF1 + GELU (all 68 blocks) =================
    {
        float*  hs  = (float*)sm;                 // 4*196
        float4* red = (float4*)(sm + 3136);       // 3 slices * 49 * 4

        const int tile  = b >> 2;        // 0..16
        const int chunk = b & 3;         // 0..3
        const int base  = tile * 4;
        const int s = tid / NG_D, gl = tid - s * NG_D;  // s 0..10 (use <4), gl<49
        const int g = chunk * NG_D + gl;                // < 196

        if (tid < 4 * NG_D) {
            int r = tid / NG_D, c = tid - r * NG_D;
            int row = base + r;
            ((float4*)hs)[r * NG_D + c] =
                (row < SEQ_) ? g_h2_4[row * NG_D + c] : make_float4(0.f, 0.f, 0.f, 0.f);
        }
        __syncthreads();

        float4 acc[4];
        #pragma unroll
        for (int r = 0; r < 4; r++) acc[r] = make_float4(0.f, 0.f, 0.f, 0.f);

        if (s < 4) {
            const int kb = s * 49;
            const float4* W = ffw1_4 + kb * NG_MLP + g;
            #pragma unroll 7
            for (int k = 0; k < 49; k++) {
                float4 w = W[k * NG_MLP];
                fma4(acc[0], hs[kb + k], w);
                fma4(acc[1], hs[D_ + kb + k], w);
                fma4(acc[2], hs[2 * D_ + kb + k], w);
                fma4(acc[3], hs[3 * D_ + kb + k], w);
            }
            if (s > 0) {
                #pragma unroll
                for (int r = 0; r < 4; r++) red[((s - 1) * NG_D + gl) * 4 + r] = acc[r];
            }
        }
        __syncthreads();
        if (s == 0) {
            float4 fb = ffb1_4[g];
            #pragma unroll
            for (int r = 0; r < 4; r++) {
                int row = base + r;
                if (row < SEQ_) {
                    float4 v = acc[r];
                    add4(v, red[(0 * NG_D + gl) * 4 + r]);
                    add4(v, red[(1 * NG_D + gl) * 4 + r]);
                    add4(v, red[(2 * NG_D + gl) * 4 + r]);
                    float4 t;
                    t.x = gelu_exact(v.x + fb.x);
                    t.y = gelu_exact(v.y + fb.y);
                    t.z = gelu_exact(v.z + fb.z);
                    t.w = gelu_exact(v.w + fb.w);
                    g_t4[row * NG_MLP + g] = t;
                }
            }
        }
    }
    gsync();

    // ================= PHASE 4: FF2 + residual -> out (blocks 0..16) =================
    if (b < 17) {
        float*  ts  = (float*)sm;                 // 4*784
        float4* red = (float4*)(sm + 12544);      // 7 slices * 49 * 4

        const int base = b * 4;
        const int s = tid / NG_D, g = tid - s * NG_D;  // s 0..10 (use <8), g<49

        for (int idx = tid; idx < 4 * NG_MLP; idx += NT_) {
            int r = idx / NG_MLP, c = idx - r * NG_MLP;
            int row = base + r;
            ((float4*)ts)[r * NG_MLP + c] =
                (row < SEQ_) ? g_t4[row * NG_MLP + c] : make_float4(0.f, 0.f, 0.f, 0.f);
        }
        __syncthreads();

        float4 acc[4];
        #pragma unroll
        for (int r = 0; r < 4; r++) acc[r] = make_float4(0.f, 0.f, 0.f, 0.f);

        if (s < 8) {
            const int kb = s * 98;
            const float4* W = ffw2_4 + kb * NG_D + g;
            const float* hb = ts + kb;
            #pragma unroll 7
            for (int k = 0; k < 98; k++) {
                float4 w = W[k * NG_D];
                fma4(acc[0], hb[k], w);
                fma4(acc[1], hb[MLP_ + k], w);
                fma4(acc[2], hb[2 * MLP_ + k], w);
                fma4(acc[3], hb[3 * MLP_ + k], w);
            }
            if (s > 0) {
                #pragma unroll
                for (int r = 0; r < 4; r++) red[((s - 1) * NG_D + g) * 4 + r] = acc[r];
            }
        }
        __syncthreads();
        if (s == 0) {
            float4 fb = ffb2_4[g];
            #pragma unroll
            for (int r = 0; r < 4; r++) {
                int row = base + r;
                if (row >= SEQ_) continue;
                float4 v = acc[r];
                #pragma unroll
                for (int ss = 0; ss < 7; ss++) add4(v, red[(ss * NG_D + g) * 4 + r]);
                float4 x2 = g_x2_4[row * NG_D + g];
                v.x += fb.x + x2.x; v.y += fb.y + x2.y;
                v.z += fb.z + x2.z; v.w += fb.w + x2.w;
                out4[row * NG_D + g] = v;
            }
        }
    }
}

// ============================================================
extern "C" void kernel_launch(void* const* d_in, const int* in_sizes, int n_in,
                              void* d_out, int out_size)
{
    const float* x      = (const float*)d_in[0];
    const float* tokens = (const float*)d_in[1];
    const float* x_pe   = (const float*)d_in[2];
    const float* conv_k = (const float*)d_in[3];
    const float* bn_g   = (const float*)d_in[4];
    const float* bn_b   = (const float*)d_in[5];
    const float* bn_rm  = (const float*)d_in[6];
    const float* bn_rv  = (const float*)d_in[7];
    const float* fc_w1  = (const float*)d_in[8];
    const float* fc_w2  = (const float*)d_in[9];
    const float* ln1_g  = (const float*)d_in[10];
    const float* ln1_b  = (const float*)d_in[11];
    const float* ln2_g  = (const float*)d_in[12];
    const float* ln2_b  = (const float*)d_in[13];
    const float* w_qkv  = (const float*)d_in[14];
    const float* w_out  = (const float*)d_in[15];
    const float* b_out  = (const float*)d_in[16];
    const float* ff_w1  = (const float*)d_in[17];
    const float* ff_b1  = (const float*)d_in[18];
    const float* ff_w2  = (const float*)d_in[19];
    const float* ff_b2  = (const float*)d_in[20];

    k_fused<<<GRID_, NT_>>>(x, tokens, x_pe, conv_k, bn_g, bn_b, bn_rm, bn_rv,
                            fc_w1, fc_w2, ln1_g, ln1_b,
                            (const float4*)w_qkv,
                            (const float4*)w_out, (const float4*)b_out,
                            (const float4*)ln2_g, (const float4*)ln2_b,
                            (const float4*)ff_w1, (const float4*)ff_b1,
                            (const float4*)ff_w2, (const float4*)ff_b2,
                            (float4*)d_out);
}

// round 10
// speedup vs baseline: 2.7009x; 1.4524x over previous
#include <cuda_runtime.h>
#include <math.h>

#define D_     196
#define NCH_   64
#define H_     8
#define DH_    64
#define INNER_ 512
#define MLP_   784
#define SEQ_   65
#define NG_QKV 384   // 1536/4
#define NG_D   49    // 196/4
#define NG_MLP 196   // 784/4
#define GRID_  100
#define NT_    512

// ---- scratch (__device__ globals; no allocations allowed) ----
__device__ float  g_a[NCH_ * D_];
__device__ float4 g_xatt4[SEQ_ * NG_D];
__device__ float4 g_qkv4[SEQ_ * NG_QKV];    // q(pre-scaled)|k|v
__device__ unsigned g_cnt;                  // barrier arrival counter (self-resetting)
__device__ unsigned g_gen;                  // barrier generation (monotonic)

__device__ __forceinline__ void fma4(float4& a, float h, const float4& w) {
    a.x += h * w.x; a.y += h * w.y; a.z += h * w.z; a.w += h * w.w;
}
__device__ __forceinline__ void add4(float4& a, const float4& b) {
    a.x += b.x; a.y += b.y; a.z += b.z; a.w += b.w;
}
__device__ __forceinline__ float gelu_exact(float v) {
    return 0.5f * v * (1.f + erff(v * 0.70710678118654752f));
}

// grid-wide barrier: safe because gridDim.x (100) <= #SMs (148), 1 block/SM
// (512 thr, <=128 regs, 20KB smem) -> all blocks co-resident.
__device__ __forceinline__ void gsync() {
    __syncthreads();
    if (threadIdx.x == 0) {
        unsigned gen = *(volatile unsigned*)&g_gen;
        __threadfence();
        if (atomicAdd(&g_cnt, 1u) == gridDim.x - 1u) {
            atomicExch(&g_cnt, 0u);
            __threadfence();
            atomicAdd(&g_gen, 1u);
        } else {
            while (*(volatile unsigned*)&g_gen == gen) { __nanosleep(32); }
        }
        __threadfence();
    }
    __syncthreads();
}

__global__ __launch_bounds__(NT_, 1) void k_fused(
    const float* __restrict__ x, const float* __restrict__ tokens,
    const float* __restrict__ x_pe, const float* __restrict__ conv_k,
    const float* __restrict__ bn_g, const float* __restrict__ bn_b,
    const float* __restrict__ bn_rm, const float* __restrict__ bn_rv,
    const float* __restrict__ fc_w1, const float* __restrict__ fc_w2,
    const float* __restrict__ ln1_g, const float* __restrict__ ln1_b,
    const float4* __restrict__ wqkv4,
    const float4* __restrict__ wout4, const float4* __restrict__ bout4,
    const float4* __restrict__ ln2g4, const float4* __restrict__ ln2b4,
    const float4* __restrict__ ffw1_4, const float4* __restrict__ ffb1_4,
    const float4* __restrict__ ffw2_4, const float4* __restrict__ ffb2_4,
    float4* __restrict__ out4)
{
    __shared__ __align__(16) char sm[20160];
    const int tid = threadIdx.x;
    const int b   = blockIdx.x;

    // ================= PHASE A: LN1 + QKV (blocks 0..98) + gating (99) =================
    if (b < 99) {
        float*  hs   = (float*)sm;                 // 2*196 floats (ends 1568)
        float4* red  = (float4*)(sm + 1600);       // 3 slices * 128 gl * 2 rows (12288 B)
        float*  mrow = (float*)(sm + 13888);       // 2
        float*  rrow = (float*)(sm + 13896);       // 2

        const int tile  = b / 3;
        const int chunk = b - tile * 3;
        const int base  = tile * 2;                // rows base, base+1

        if (tid < 2 * D_) {
            int r = tid / D_, c = tid - r * D_;
            int row = base + r;
            hs[tid] = (row < SEQ_) ? x[row * D_ + c] : 0.f;
        }
        __syncthreads();

        const int warp = tid >> 5, lane = tid & 31;
        if (warp < 2) {
            float s1 = 0.f, s2 = 0.f;
            #pragma unroll
            for (int i = 0; i < 7; i++) {
                int c = lane + 32 * i;
                if (c < D_) { float v = hs[warp * D_ + c]; s1 += v; s2 += v * v; }
            }
            #pragma unroll
            for (int o = 16; o; o >>= 1) {
                s1 += __shfl_down_sync(0xffffffffu, s1, o);
                s2 += __shfl_down_sync(0xffffffffu, s2, o);
            }
            if (lane == 0) {
                float mean = s1 * (1.f / 196.f);
                float var  = s2 * (1.f / 196.f) - mean * mean;
                mrow[warp] = mean; rrow[warp] = rsqrtf(var + 1e-5f);
            }
        }
        __syncthreads();
        if (tid < 2 * D_) {
            int r = tid / D_, c = tid - r * D_;
            hs[tid] = (hs[tid] - mrow[r]) * rrow[r] * ln1_g[c] + ln1_b[c];
        }
        __syncthreads();

        const int gl = tid & 127;
        const int g  = chunk * 128 + gl;     // < 384
        const int s  = tid >> 7;             // K-slice 0..3, each 49
        float4 a0 = make_float4(0.f, 0.f, 0.f, 0.f);
        float4 a1 = make_float4(0.f, 0.f, 0.f, 0.f);

        const int kb = s * 49;
        const float4* W = wqkv4 + kb * NG_QKV + g;
        #pragma unroll 7
        for (int k = 0; k < 49; k++) {
            float4 w = W[k * NG_QKV];
            fma4(a0, hs[kb + k], w);
            fma4(a1, hs[D_ + kb + k], w);
        }
        if (s > 0) {
            red[((s - 1) * 128 + gl) * 2 + 0] = a0;
            red[((s - 1) * 128 + gl) * 2 + 1] = a1;
        }
        __syncthreads();
        if (s == 0) {
            float sc = (g < 128) ? 0.125f : 1.f;   // q pre-scale DH^-0.5
            #pragma unroll
            for (int ss = 0; ss < 3; ss++) {
                add4(a0, red[(ss * 128 + gl) * 2 + 0]);
                add4(a1, red[(ss * 128 + gl) * 2 + 1]);
            }
            a0.x *= sc; a0.y *= sc; a0.z *= sc; a0.w *= sc;
            a1.x *= sc; a1.y *= sc; a1.z *= sc; a1.w *= sc;
            if (base < SEQ_)     g_qkv4[base * NG_QKV + g]       = a0;
            if (base + 1 < SEQ_) g_qkv4[(base + 1) * NG_QKV + g] = a1;
        }
    } else {
        // ---------------- gating (block 99) ----------------
        float* b1s = (float*)sm;              // 64
        float* b2s = (float*)(sm + 256);      // 64
        float* hid = (float*)(sm + 512);      // 12
        float* cs  = (float*)(sm + 576);      // 64

        const int warp = tid >> 5, lane = tid & 31;
        const float k0 = conv_k[3], k1 = conv_k[4], k2 = conv_k[5];
        const float rm  = bn_rm[0];
        const float inv = rsqrtf(bn_rv[0] + 1e-5f) * bn_g[0];
        const float bb  = bn_b[0];

        for (int ch = warp; ch < NCH_; ch += 16) {
            const float* row = x_pe + ch * D_;
            float s = 0.f;
            for (int d = lane; d < D_; d += 32) {
                float xm = (d > 0)      ? row[d - 1] : 0.f;
                float xc = row[d];
                float xp = (d < D_ - 1) ? row[d + 1] : 0.f;
                float conv = k0 * xm + k1 * xc + k2 * xp;
                float bn = (conv - rm) * inv + bb;
                float av = fmaxf(bn, 0.f);
                g_a[ch * D_ + d] = av;
                s += av;
            }
            #pragma unroll
            for (int o = 16; o; o >>= 1) s += __shfl_down_sync(0xffffffffu, s, o);
            if (lane == 0) b1s[ch] = s * (1.f / 196.f);
        }
        __syncthreads();

        if (tid < NCH_) {
            const float bi = b1s[tid];
            float mx = -1e30f, mn = 1e30f;
            int cnt_nonpos = 0, rank = 0;
            #pragma unroll 8
            for (int j = 0; j < NCH_; j++) {
                float bj = b1s[j];
                mx = fmaxf(mx, bj); mn = fminf(mn, bj);
                if (bj <= 0.f) cnt_nonpos++;
                if (bj < bi || (bj == bi && j < tid)) rank++;
            }
            int middle = (mx < 0.f || mn > 0.f) ? 32 : (mx > 0.f ? cnt_nonpos : 0);
            float b2;
            if (rank < middle) {
                float ls = (float)middle;
                b2 = bi - 1.f / (1.f + powf(ls, bi));
            } else {
                float le = (float)(NCH_ - middle);
                b2 = bi + 1.f / (1.f + powf(le, -bi));
            }
            b2s[tid] = b2;
        }
        __syncthreads();
        if (tid < 12) {
            float s = 0.f;
            #pragma unroll 8
            for (int i = 0; i < NCH_; i++) s += b2s[i] * fc_w1[i * 12 + tid];
            hid[tid] = fmaxf(s, 0.f);
        }
        __syncthreads();
        if (tid < NCH_) {
            float s = 0.f;
            #pragma unroll
            for (int j = 0; j < 12; j++) s += hid[j] * fc_w2[j * NCH_ + tid];
            cs[tid] = 1.f / (1.f + expf(-s));
        }
        __syncthreads();
        float* xatt = (float*)g_xatt4;
        for (int idx = tid; idx < NCH_ * D_; idx += NT_)
            xatt[idx] = g_a[idx] * cs[idx / D_];
        for (int d = tid; d < D_; d += NT_)
            xatt[NCH_ * D_ + d] = tokens[d];
    }
    gsync();   // the ONLY grid barrier

    // ================= PHASE B: per-row pipeline (blocks 0..64) =================
    if (b >= SEQ_) return;
    const int n = b;
    const float* qkv = (const float*)g_qkv4;

    float*  qs    = (float*)sm;                // 512 f          [0,2048)
    float*  scs   = (float*)(sm + 2048);       // 8*66 f         [2048,4160)
    float*  smaxp = (float*)(sm + 4160);       // 8
    float*  sinvp = (float*)(sm + 4192);       // 8
    float*  os    = (float*)(sm + 4224);       // 512 f          [4224,6272)
    float4* red   = (float4*)(sm + 6272);      // 7*49 f4        [6272,11760)
    float4* x2s   = (float4*)(sm + 11760);     // 49 f4          [11760,12544)
    float4* h2s   = (float4*)(sm + 12544);     // 49 f4          [12544,13328)
    float*  p1    = (float*)(sm + 13328);      // 49
    float*  p2    = (float*)(sm + 13524);      // 49
    float*  stats = (float*)(sm + 13720);      // 2
    float4* ts4   = (float4*)(sm + 13744);     // 196 f4         [13744,16880)
    float4* red1  = (float4*)(sm + 16880);     // 196 f4         [16880,20016)

    // ---- attention: head h = tid>>6, lane-within-head d = tid&63 ----
    const int h = tid >> 6, d = tid & 63;
    qs[tid] = qkv[n * 1536 + tid];            // q row (pre-scaled)
    __syncthreads();

    const float* qh = qs + h * DH_;
    {
        const float4* kr = (const float4*)(qkv + d * 1536 + INNER_ + h * DH_);
        float s = 0.f;
        #pragma unroll
        for (int i = 0; i < 16; i++) {
            float4 k4 = kr[i];
            s += qh[4*i] * k4.x + qh[4*i+1] * k4.y + qh[4*i+2] * k4.z + qh[4*i+3] * k4.w;
        }
        scs[h * 66 + d] = s;
        if (d == 0) {
            const float4* kr2 = (const float4*)(qkv + 64 * 1536 + INNER_ + h * DH_);
            float s2 = 0.f;
            #pragma unroll
            for (int i = 0; i < 16; i++) {
                float4 k4 = kr2[i];
                s2 += qh[4*i] * k4.x + qh[4*i+1] * k4.y + qh[4*i+2] * k4.z + qh[4*i+3] * k4.w;
            }
            scs[h * 66 + 64] = s2;
        }
    }
    __syncthreads();
    if (d < 32) {
        float m = fmaxf(scs[h * 66 + d], scs[h * 66 + d + 32]);
        if (d == 0) m = fmaxf(m, scs[h * 66 + 64]);
        #pragma unroll
        for (int o = 16; o; o >>= 1) m = fmaxf(m, __shfl_down_sync(0xffffffffu, m, o));
        if (d == 0) smaxp[h] = m;
    }
    __syncthreads();
    {
        float mx = smaxp[h];
        scs[h * 66 + d] = expf(scs[h * 66 + d] - mx);
        if (d == 0) scs[h * 66 + 64] = expf(scs[h * 66 + 64] - mx);
    }
    __syncthreads();
    if (d < 32) {
        float s = scs[h * 66 + d] + scs[h * 66 + d + 32];
        if (d == 0) s += scs[h * 66 + 64];
        #pragma unroll
        for (int o = 16; o; o >>= 1) s += __shfl_down_sync(0xffffffffu, s, o);
        if (d == 0) sinvp[h] = 1.f / s;
    }
    __syncthreads();
    {
        const float* vb = qkv + 2 * INNER_ + h * DH_ + d;
        const float* p  = scs + h * 66;
        float acc = 0.f;
        #pragma unroll 8
        for (int m = 0; m < SEQ_; m++) acc += p[m] * vb[m * 1536];
        os[tid] = acc * sinvp[h];
    }
    __syncthreads();

    // ---- out-proj (K=512, 8 slices of 64) + residuals + LN2 ----
    const int s8 = tid / NG_D;                 // 0..10 (use <8)
    const int g  = tid - s8 * NG_D;            // <49
    float4 vacc = make_float4(0.f, 0.f, 0.f, 0.f);
    if (s8 < 8) {
        const int kb = s8 * 64;
        const float4* W = wout4 + kb * NG_D + g;
        const float* hb = os + kb;
        #pragma unroll 8
        for (int k = 0; k < 64; k++) fma4(vacc, hb[k], W[k * NG_D]);
        if (s8 > 0) red[(s8 - 1) * NG_D + g] = vacc;
    }
    __syncthreads();
    if (s8 == 0) {
        #pragma unroll
        for (int ss = 0; ss < 7; ss++) add4(vacc, red[ss * NG_D + g]);
        float4 bo = bout4[g];
        float4 xv = ((const float4*)x)[n * NG_D + g];
        float4 xa = g_xatt4[n * NG_D + g];
        vacc.x += bo.x + xv.x + xa.x;
        vacc.y += bo.y + xv.y + xa.y;
        vacc.z += bo.z + xv.z + xa.z;
        vacc.w += bo.w + xv.w + xa.w;
        x2s[g] = vacc;
        p1[g] = vacc.x + vacc.y + vacc.z + vacc.w;
        p2[g] = vacc.x*vacc.x + vacc.y*vacc.y + vacc.z*vacc.z + vacc.w*vacc.w;
    }
    __syncthreads();
    if (tid < 32) {
        float t1 = 0.f, t2 = 0.f;
        for (int i = tid; i < NG_D; i += 32) { t1 += p1[i]; t2 += p2[i]; }
        #pragma unroll
        for (int o = 16; o; o >>= 1) {
            t1 += __shfl_down_sync(0xffffffffu, t1, o);
            t2 += __shfl_down_sync(0xffffffffu, t2, o);
        }
        if (tid == 0) {
            float mean = t1 * (1.f / 196.f);
            float var  = t2 * (1.f / 196.f) - mean * mean;
            stats[0] = mean; stats[1] = rsqrtf(var + 1e-5f);
        }
    }
    __syncthreads();
    if (s8 == 0) {
        float m = stats[0], rs = stats[1];
        float4 v = x2s[g], gg = ln2g4[g], bb = ln2b4[g], hh;
        hh.x = (v.x - m) * rs * gg.x + bb.x;
        hh.y = (v.y - m) * rs * gg.y + bb.y;
        hh.z = (v.z - m) * rs * gg.z + bb.z;
        hh.w = (v.w - m) * rs * gg.w + bb.w;
        h2s[g] = hh;
    }
    __syncthreads();

    // ---- FF1 (K=196, 2 slices of 98) + GELU ----
    float4 facc = make_float4(0.f, 0.f, 0.f, 0.f);
    if (tid < 392) {
        const int s1 = tid / NG_MLP;           // 0..1
        const int gg = tid - s1 * NG_MLP;      // <196
        const float* hh = (const float*)h2s;   // 196 floats
        const int kb = s1 * 98;
        const float4* W = ffw1_4 + kb * NG_MLP + gg;
        #pragma unroll 7
        for (int k = 0; k < 98; k++) fma4(facc, hh[kb + k], W[k * NG_MLP]);
        if (s1 == 1) red1[gg] = facc;
    }
    __syncthreads();
    if (tid < NG_MLP) {
        add4(facc, red1[tid]);
        float4 fb = ffb1_4[tid], t;
        t.x = gelu_exact(facc.x + fb.x);
        t.y = gelu_exact(facc.y + fb.y);
        t.z = gelu_exact(facc.z + fb.z);
        t.w = gelu_exact(facc.w + fb.w);
        ts4[tid] = t;
    }
    __syncthreads();

    // ---- FF2 (K=784, 8 slices of 98) + residual -> out ----
    float4 oacc = make_float4(0.f, 0.f, 0.f, 0.f);
    if (s8 < 8) {
        const int kb = s8 * 98;
        const float* tf = (const float*)ts4;   // 784 floats
        const float4* W = ffw2_4 + kb * NG_D + g;
        #pragma unroll 7
        for (int k = 0; k < 98; k++) fma4(oacc, tf[kb + k], W[k * NG_D]);
        if (s8 > 0) red[(s8 - 1) * NG_D + g] = oacc;
    }
    __syncthreads();
    if (s8 == 0) {
        #pragma unroll
        for (int ss = 0; ss < 7; ss++) add4(oacc, red[ss * NG_D + g]);
        float4 fb = ffb2_4[g], x2 = x2s[g];
        oacc.x += fb.x + x2.x; oacc.y += fb.y + x2.y;
        oacc.z += fb.z + x2.z; oacc.w += fb.w + x2.w;
        out4[n * NG_D + g] = oacc;
    }
}

// ============================================================
extern "C" void kernel_launch(void* const* d_in, const int* in_sizes, int n_in,
                              void* d_out, int out_size)
{
    const float* x      = (const float*)d_in[0];
    const float* tokens = (const float*)d_in[1];
    const float* x_pe   = (const float*)d_in[2];
    const float* conv_k = (const float*)d_in[3];
    const float* bn_g   = (const float*)d_in[4];
    const float* bn_b   = (const float*)d_in[5];
    const float* bn_rm  = (const float*)d_in[6];
    const float* bn_rv  = (const float*)d_in[7];
    const float* fc_w1  = (const float*)d_in[8];
    const float* fc_w2  = (const float*)d_in[9];
    const float* ln1_g  = (const float*)d_in[10];
    const float* ln1_b  = (const float*)d_in[11];
    const float* ln2_g  = (const float*)d_in[12];
    const float* ln2_b  = (const float*)d_in[13];
    const float* w_qkv  = (const float*)d_in[14];
    const float* w_out  = (const float*)d_in[15];
    const float* b_out  = (const float*)d_in[16];
    const float* ff_w1  = (const float*)d_in[17];
    const float* ff_b1  = (const float*)d_in[18];
    const float* ff_w2  = (const float*)d_in[19];
    const float* ff_b2  = (const float*)d_in[20];

    k_fused<<<GRID_, NT_>>>(x, tokens, x_pe, conv_k, bn_g, bn_b, bn_rm, bn_rv,
                            fc_w1, fc_w2, ln1_g, ln1_b,
                            (const float4*)w_qkv,
                            (const float4*)w_out, (const float4*)b_out,
                            (const float4*)ln2_g, (const float4*)ln2_b,
                            (const float4*)ff_w1, (const float4*)ff_b1,
                            (const float4*)ff_w2, (const float4*)ff_b2,
                            (float4*)d_out);
}